// round 14
// baseline (speedup 1.0000x reference)
#include <cuda_runtime.h>
#include <cuda_fp16.h>
#include <math.h>
#include <cstdint>

#define EPS_BN 1e-3f

static constexpr int B_  = 4096;
static constexpr int TXN = 32;
static constexpr int SUB = 13;
static constexpr int R   = B_ * SUB;   // 53248 rows per tower

// -------------------- scratch (alloc-free: __device__ globals) --------------------
__device__ __half g_X [(size_t)2 * R * 64];
__device__ __half g_A [(size_t)2 * R * 1024];
__device__ __half g_Bf[(size_t)2 * R * 512];
__device__ __half g_W1t[(size_t)2 * 1024 * 64];
__device__ __half g_W2t[(size_t)2 * 512 * 1024];
__device__ __half g_W3t[(size_t)2 * 512 * 512];
__device__ __half g_W4t[(size_t)2 * 64 * 512];

// -------------------- helpers --------------------
__device__ __forceinline__ uint32_t smem_u32(const void* p) {
    uint32_t a;
    asm("{ .reg .u64 t; cvta.to.shared.u64 t, %1; cvt.u32.u64 %0, t; }" : "=r"(a) : "l"(p));
    return a;
}
#define CP16(dst, src) \
    asm volatile("cp.async.cg.shared.global [%0], [%1], 16;" :: "r"(dst), "l"(src))
#define CP_COMMIT() asm volatile("cp.async.commit_group;" ::: "memory")

__device__ __forceinline__ void ldsm_x4(uint32_t& r0, uint32_t& r1, uint32_t& r2,
                                        uint32_t& r3, uint32_t addr) {
    asm volatile("ldmatrix.sync.aligned.m8n8.x4.shared.b16 {%0,%1,%2,%3}, [%4];"
        : "=r"(r0), "=r"(r1), "=r"(r2), "=r"(r3) : "r"(addr));
}
__device__ __forceinline__ void mma_f16(float& c0, float& c1, float& c2, float& c3,
                                        uint32_t a0, uint32_t a1, uint32_t a2, uint32_t a3,
                                        uint32_t b0, uint32_t b1) {
    asm volatile(
        "mma.sync.aligned.m16n8k16.row.col.f32.f16.f16.f32 "
        "{%0,%1,%2,%3}, {%4,%5,%6,%7}, {%8,%9}, {%0,%1,%2,%3};"
        : "+f"(c0), "+f"(c1), "+f"(c2), "+f"(c3)
        : "r"(a0), "r"(a1), "r"(a2), "r"(a3), "r"(b0), "r"(b1));
}

// -------------------- merged prologue: input norm + all weight transposes ---------
__global__ void prologue_kernel(const float* __restrict__ V1, const float* __restrict__ V2,
                                __half* __restrict__ X,
                                const float* __restrict__ W1, const float* __restrict__ W2,
                                const float* __restrict__ W3, const float* __restrict__ W4,
                                __half* __restrict__ W1t, __half* __restrict__ W2t,
                                __half* __restrict__ W3t, __half* __restrict__ W4t) {
    if (blockIdx.x < R / 4) {
        int sub = threadIdx.x >> 6;
        int pair = blockIdx.x * 4 + sub;
        int b = pair / SUB, s = pair % SUB;
        int o = threadIdx.x & 63;
        int warp = o >> 5, lane = o & 31;
        const float* V = (warp == 0) ? V1 : V2;
        int base = ((b * TXN + lane) * SUB + s) * 2;
        float c0 = V[base], c1 = V[base + 1];
        float ss = c0 * c0 + c1 * c1;
        #pragma unroll
        for (int off = 16; off; off >>= 1) ss += __shfl_xor_sync(0xFFFFFFFFu, ss, off);
        float inv = rsqrtf(ss);
        X[((size_t)0 * R + pair) * 64 + o] = __float2half_rn(c0 * inv);
        X[((size_t)1 * R + pair) * 64 + o] = __float2half_rn(c1 * inv);
        return;
    }
    __shared__ float tile[32][33];
    int idx = blockIdx.x - R / 4;
    int t = idx / 864, bid = idx % 864;
    const float* W; __half* Wt; int K, N, rem;
    if (bid < 64)       { W = W1; Wt = W1t; K = 64;   N = 1024; rem = bid; }
    else if (bid < 576) { W = W2; Wt = W2t; K = 1024; N = 512;  rem = bid - 64; }
    else if (bid < 832) { W = W3; Wt = W3t; K = 512;  N = 512;  rem = bid - 576; }
    else                { W = W4; Wt = W4t; K = 512;  N = 64;   rem = bid - 832; }
    int nb = N / 32;
    int k0 = (rem / nb) * 32, n0 = (rem % nb) * 32;
    const float* Wp = W + (size_t)t * K * N;
    __half* Wtp = Wt + (size_t)t * N * K;
    int x = threadIdx.x & 31, y = threadIdx.x >> 5;
    #pragma unroll
    for (int dy = 0; dy < 32; dy += 8)
        tile[y + dy][x] = Wp[(size_t)(k0 + y + dy) * N + n0 + x];
    __syncthreads();
    #pragma unroll
    for (int dy = 0; dy < 32; dy += 8)
        Wtp[(size_t)(n0 + y + dy) * K + k0 + x] = __float2half_rn(tile[x][y + dy]);
}

// -------------------- FP16 mma GEMM + fused bias/ReLU/BN (layers 2,3) -------------
// 4 warps (2x2), warp tile 64x64, BK=64, 3-stage cp.async pipeline, 2 CTAs/SM. (R12)
template <int BN>
__global__ void __launch_bounds__(128, 2)
gemm_h(const __half* __restrict__ A, const __half* __restrict__ Wt,
       const float* __restrict__ bias, const float* __restrict__ gg,
       const float* __restrict__ bbe, const float* __restrict__ mm,
       const float* __restrict__ vv, __half* __restrict__ C,
       int K, int N) {
    constexpr int BM = 128, BK = 64, STAGES = 3;
    constexpr int WN = BN / 2;
    constexpr int MT = 4;
    constexpr int NT = WN / 8;
    constexpr int STG_A = BM * BK;
    constexpr int STG   = (BM + BN) * BK;

    extern __shared__ __half smem[];
    const uint32_t sb = smem_u32(smem);

    const int tid  = threadIdx.x;
    const int wid  = tid >> 5, lane = tid & 31;
    const int grp  = lane >> 2, tig = lane & 3;
    const int wm   = wid & 1, wn = wid >> 1;
    const int t    = blockIdx.z;
    const int bm   = blockIdx.y * BM;
    const int bn   = blockIdx.x * BN;

    A  += (size_t)t * R * K;
    Wt += (size_t)t * N * K;
    bias += (size_t)t * N;
    gg += (size_t)t * N; bbe += (size_t)t * N; mm += (size_t)t * N; vv += (size_t)t * N;

    const int iters = K / BK;

    auto load_tiles = [&](int it) {
        const int k0 = it * BK;
        __half* d = smem + (it % STAGES) * STG;
        uint32_t dA = smem_u32(d), dB = dA + STG_A * 2;
        #pragma unroll
        for (int p = 0; p < 8; p++) {
            int idx = p * 128 + tid;
            int r = idx >> 3, c = idx & 7;
            CP16(dA + r * 128 + ((c ^ (r & 7)) << 4),
                 A + (size_t)(bm + r) * K + k0 + c * 8);
        }
        #pragma unroll
        for (int p = 0; p < BN / 16; p++) {
            int idx = p * 128 + tid;
            int r = idx >> 3, c = idx & 7;
            CP16(dB + r * 128 + ((c ^ (r & 7)) << 4),
                 Wt + (size_t)(bn + r) * K + k0 + c * 8);
        }
    };

    float acc[MT][NT][4];
    #pragma unroll
    for (int i = 0; i < MT; i++)
        #pragma unroll
        for (int j = 0; j < NT; j++)
            acc[i][j][0] = acc[i][j][1] = acc[i][j][2] = acc[i][j][3] = 0.f;

    #pragma unroll
    for (int s = 0; s < STAGES - 1; s++) {
        if (s < iters) load_tiles(s);
        CP_COMMIT();
    }

    const int s3     = lane & 7;
    const uint32_t a_rb = (uint32_t)((wm * 64 + (lane & 7) + ((lane >> 3) & 1) * 8) * 128);
    const int a_csel = lane >> 4;
    const uint32_t b_rb = (uint32_t)((wn * WN + (lane & 7) + ((lane >> 4) & 1) * 8) * 128);
    const int b_csel = (lane >> 3) & 1;

    for (int it = 0; it < iters; ++it) {
        asm volatile("cp.async.wait_group 1;" ::: "memory");
        __syncthreads();
        {
            int nxt = it + STAGES - 1;
            if (nxt < iters) load_tiles(nxt);
            CP_COMMIT();
        }

        const uint32_t aB = sb + (it % STAGES) * STG * 2;
        const uint32_t bB = aB + STG_A * 2;

        #pragma unroll
        for (int ks = 0; ks < BK / 16; ks++) {
            const uint32_t aAddr = aB + a_rb + (uint32_t)(((ks * 2 + a_csel) ^ s3) << 4);
            const uint32_t bAddr = bB + b_rb + (uint32_t)(((ks * 2 + b_csel) ^ s3) << 4);
            uint32_t af[MT][4], bf[NT][2];
            #pragma unroll
            for (int mi = 0; mi < MT; mi++)
                ldsm_x4(af[mi][0], af[mi][1], af[mi][2], af[mi][3],
                        aAddr + mi * (16 * 128));
            #pragma unroll
            for (int nb = 0; nb < NT / 2; nb++)
                ldsm_x4(bf[2 * nb][0], bf[2 * nb][1], bf[2 * nb + 1][0], bf[2 * nb + 1][1],
                        bAddr + nb * (16 * 128));
            #pragma unroll
            for (int mi = 0; mi < MT; mi++)
                #pragma unroll
                for (int ni = 0; ni < NT; ni++)
                    mma_f16(acc[mi][ni][0], acc[mi][ni][1], acc[mi][ni][2], acc[mi][ni][3],
                            af[mi][0], af[mi][1], af[mi][2], af[mi][3],
                            bf[ni][0], bf[ni][1]);
        }
    }

    #pragma unroll
    for (int ni = 0; ni < NT; ni++) {
        const int col = bn + wn * WN + ni * 8 + tig * 2;
        float pb0 = __ldg(&bias[col]), pb1 = __ldg(&bias[col + 1]);
        float pm0 = __ldg(&mm[col]),  pm1 = __ldg(&mm[col + 1]);
        float ps0 = __ldg(&gg[col])     * rsqrtf(__ldg(&vv[col])     + EPS_BN);
        float ps1 = __ldg(&gg[col + 1]) * rsqrtf(__ldg(&vv[col + 1]) + EPS_BN);
        float pe0 = __ldg(&bbe[col]), pe1 = __ldg(&bbe[col + 1]);
        #pragma unroll
        for (int mi = 0; mi < MT; mi++) {
            #pragma unroll
            for (int h = 0; h < 2; h++) {
                const int row = bm + wm * 64 + mi * 16 + grp + h * 8;
                float v0 = fmaxf(acc[mi][ni][h * 2 + 0] + pb0, 0.f);
                float v1 = fmaxf(acc[mi][ni][h * 2 + 1] + pb1, 0.f);
                v0 = (v0 - pm0) * ps0 + pe0;
                v1 = (v1 - pm1) * ps1 + pe1;
                *(__half2*)(C + (size_t)t * R * N + (size_t)row * N + col)
                    = __floats2half2_rn(v0, v1);
            }
        }
    }
}

// -------------------- specialized layer-1 GEMM: K=64, A register-resident ---------
// A (128x64) loaded once -> LDSM -> 64 regs; B streamed over 8 bn-tiles, 3-stage.
__global__ void __launch_bounds__(128, 2)
gemm_l1(const __half* __restrict__ A, const __half* __restrict__ Wt,
        const float* __restrict__ bias, const float* __restrict__ gg,
        const float* __restrict__ bbe, const float* __restrict__ mm,
        const float* __restrict__ vv, __half* __restrict__ C) {
    constexpr int BM = 128, BN = 128, K = 64, N = 1024, STAGES = 3;
    constexpr int WN = 64, MT = 4, NT = 8;
    constexpr int NTILES = N / BN;                 // 8
    constexpr int BSTG   = BN * K;                 // halves per B stage (16 KB)

    extern __shared__ __half smem[];               // [A 16KB][B stages 3x16KB]
    const uint32_t sb = smem_u32(smem);
    const uint32_t sbB = sb + BM * K * 2;

    const int tid  = threadIdx.x;
    const int wid  = tid >> 5, lane = tid & 31;
    const int grp  = lane >> 2, tig = lane & 3;
    const int wm   = wid & 1, wn = wid >> 1;
    const int t    = blockIdx.z;
    const int bm   = blockIdx.y * BM;

    A  += (size_t)t * R * K;
    Wt += (size_t)t * N * K;
    bias += (size_t)t * N;
    gg += (size_t)t * N; bbe += (size_t)t * N; mm += (size_t)t * N; vv += (size_t)t * N;

    // load A once (group 0)
    #pragma unroll
    for (int p = 0; p < 8; p++) {
        int idx = p * 128 + tid;
        int r = idx >> 3, c = idx & 7;
        CP16(sb + r * 128 + ((c ^ (r & 7)) << 4),
             A + (size_t)(bm + r) * K + c * 8);
    }
    CP_COMMIT();

    auto load_B = [&](int tile) {
        uint32_t dB = sbB + (tile % STAGES) * BSTG * 2;
        const int bn = tile * BN;
        #pragma unroll
        for (int p = 0; p < 8; p++) {
            int idx = p * 128 + tid;
            int r = idx >> 3, c = idx & 7;
            CP16(dB + r * 128 + ((c ^ (r & 7)) << 4),
                 Wt + (size_t)(bn + r) * K + c * 8);
        }
    };
    load_B(0); CP_COMMIT();
    load_B(1); CP_COMMIT();

    const int s3     = lane & 7;
    const uint32_t a_rb = (uint32_t)((wm * 64 + (lane & 7) + ((lane >> 3) & 1) * 8) * 128);
    const int a_csel = lane >> 4;
    const uint32_t b_rb = (uint32_t)((wn * WN + (lane & 7) + ((lane >> 4) & 1) * 8) * 128);
    const int b_csel = (lane >> 3) & 1;

    // wait for A (2 B-groups still pending), sync, load A frags to registers
    asm volatile("cp.async.wait_group 2;" ::: "memory");
    __syncthreads();
    uint32_t afr[4][MT][4];
    #pragma unroll
    for (int ks = 0; ks < 4; ks++) {
        const uint32_t aAddr = sb + a_rb + (uint32_t)(((ks * 2 + a_csel) ^ s3) << 4);
        #pragma unroll
        for (int mi = 0; mi < MT; mi++)
            ldsm_x4(afr[ks][mi][0], afr[ks][mi][1], afr[ks][mi][2], afr[ks][mi][3],
                    aAddr + mi * (16 * 128));
    }

    #pragma unroll
    for (int tile = 0; tile < NTILES; ++tile) {
        asm volatile("cp.async.wait_group 1;" ::: "memory");
        __syncthreads();
        {
            int nxt = tile + STAGES - 1;
            if (nxt < NTILES) load_B(nxt);
            CP_COMMIT();
        }

        float acc[MT][NT][4];
        #pragma unroll
        for (int i = 0; i < MT; i++)
            #pragma unroll
            for (int j = 0; j < NT; j++)
                acc[i][j][0] = acc[i][j][1] = acc[i][j][2] = acc[i][j][3] = 0.f;

        const uint32_t bB = sbB + (tile % STAGES) * BSTG * 2;
        #pragma unroll
        for (int ks = 0; ks < 4; ks++) {
            const uint32_t bAddr = bB + b_rb + (uint32_t)(((ks * 2 + b_csel) ^ s3) << 4);
            uint32_t bf[NT][2];
            #pragma unroll
            for (int nb = 0; nb < NT / 2; nb++)
                ldsm_x4(bf[2 * nb][0], bf[2 * nb][1], bf[2 * nb + 1][0], bf[2 * nb + 1][1],
                        bAddr + nb * (16 * 128));
            #pragma unroll
            for (int mi = 0; mi < MT; mi++)
                #pragma unroll
                for (int ni = 0; ni < NT; ni++)
                    mma_f16(acc[mi][ni][0], acc[mi][ni][1], acc[mi][ni][2], acc[mi][ni][3],
                            afr[ks][mi][0], afr[ks][mi][1], afr[ks][mi][2], afr[ks][mi][3],
                            bf[ni][0], bf[ni][1]);
        }

        // epilogue for this tile (overlaps next B prefetch)
        const int bn = tile * BN;
        #pragma unroll
        for (int ni = 0; ni < NT; ni++) {
            const int col = bn + wn * WN + ni * 8 + tig * 2;
            float pb0 = __ldg(&bias[col]), pb1 = __ldg(&bias[col + 1]);
            float pm0 = __ldg(&mm[col]),  pm1 = __ldg(&mm[col + 1]);
            float ps0 = __ldg(&gg[col])     * rsqrtf(__ldg(&vv[col])     + EPS_BN);
            float ps1 = __ldg(&gg[col + 1]) * rsqrtf(__ldg(&vv[col + 1]) + EPS_BN);
            float pe0 = __ldg(&bbe[col]), pe1 = __ldg(&bbe[col + 1]);
            #pragma unroll
            for (int mi = 0; mi < MT; mi++) {
                #pragma unroll
                for (int h = 0; h < 2; h++) {
                    const int row = bm + wm * 64 + mi * 16 + grp + h * 8;
                    float v0 = fmaxf(acc[mi][ni][h * 2 + 0] + pb0, 0.f);
                    float v1 = fmaxf(acc[mi][ni][h * 2 + 1] + pb1, 0.f);
                    v0 = (v0 - pm0) * ps0 + pe0;
                    v1 = (v1 - pm1) * ps1 + pe1;
                    *(__half2*)(C + (size_t)t * R * N + (size_t)row * N + col)
                        = __floats2half2_rn(v0, v1);
                }
            }
        }
    }
}

// -------------------- fused layer-4 GEMM (both towers) + sigmoid/L2-norm head -----
// CTA: 64 rows x 64 cols, K=512, towers sequential (832 CTAs). (R12)
__global__ void __launch_bounds__(128, 2)
gemm4_head(const __half* __restrict__ A, const __half* __restrict__ Wt,
           const float* __restrict__ bias, float* __restrict__ out) {
    constexpr int BM = 64, BK = 64, STAGES = 3, K = 512, N = 64;
    constexpr int WN = 32, MT = 2, NT = 4;
    constexpr int STG_A = BM * BK;
    constexpr int STG   = (BM + 64) * BK;
    constexpr int ITERS = K / BK;

    extern __shared__ __half smem[];
    const uint32_t sb = smem_u32(smem);
    float* ssum = (float*)(smem + STAGES * STG);

    const int tid  = threadIdx.x;
    const int wid  = tid >> 5, lane = tid & 31;
    const int grp  = lane >> 2, tig = lane & 3;
    const int wm   = wid & 1, wn = wid >> 1;
    const int bm   = blockIdx.y * BM;

    const int s3     = lane & 7;
    const uint32_t a_rb = (uint32_t)((wm * 32 + (lane & 7) + ((lane >> 3) & 1) * 8) * 128);
    const int a_csel = lane >> 4;
    const uint32_t b_rb = (uint32_t)((wn * WN + (lane & 7) + ((lane >> 4) & 1) * 8) * 128);
    const int b_csel = (lane >> 3) & 1;

    float acc[2][MT][NT][4];
    #pragma unroll
    for (int t = 0; t < 2; t++)
        #pragma unroll
        for (int i = 0; i < MT; i++)
            #pragma unroll
            for (int j = 0; j < NT; j++)
                acc[t][i][j][0] = acc[t][i][j][1] = acc[t][i][j][2] = acc[t][i][j][3] = 0.f;

    auto load_tiles = [&](const __half* Ap, const __half* Wp, int it) {
        const int k0 = it * BK;
        __half* d = smem + (it % STAGES) * STG;
        uint32_t dA = smem_u32(d), dB = dA + STG_A * 2;
        #pragma unroll
        for (int p = 0; p < 4; p++) {
            int idx = p * 128 + tid;
            int r = idx >> 3, c = idx & 7;
            CP16(dA + r * 128 + ((c ^ (r & 7)) << 4),
                 Ap + (size_t)(bm + r) * K + k0 + c * 8);
        }
        #pragma unroll
        for (int p = 0; p < 4; p++) {
            int idx = p * 128 + tid;
            int r = idx >> 3, c = idx & 7;
            CP16(dB + r * 128 + ((c ^ (r & 7)) << 4),
                 Wp + (size_t)r * K + k0 + c * 8);
        }
    };

    #pragma unroll
    for (int t = 0; t < 2; t++) {
        const __half* Ap = A  + (size_t)t * R * K;
        const __half* Wp = Wt + (size_t)t * N * K;

        load_tiles(Ap, Wp, 0); CP_COMMIT();
        load_tiles(Ap, Wp, 1); CP_COMMIT();

        for (int it = 0; it < ITERS; ++it) {
            asm volatile("cp.async.wait_group 1;" ::: "memory");
            __syncthreads();
            {
                int nxt = it + STAGES - 1;
                if (nxt < ITERS) load_tiles(Ap, Wp, nxt);
                CP_COMMIT();
            }
            const uint32_t aB = sb + (it % STAGES) * STG * 2;
            const uint32_t bB = aB + STG_A * 2;
            #pragma unroll
            for (int ks = 0; ks < BK / 16; ks++) {
                const uint32_t aAddr = aB + a_rb + (uint32_t)(((ks * 2 + a_csel) ^ s3) << 4);
                const uint32_t bAddr = bB + b_rb + (uint32_t)(((ks * 2 + b_csel) ^ s3) << 4);
                uint32_t af[MT][4], bf[NT][2];
                #pragma unroll
                for (int mi = 0; mi < MT; mi++)
                    ldsm_x4(af[mi][0], af[mi][1], af[mi][2], af[mi][3],
                            aAddr + mi * (16 * 128));
                #pragma unroll
                for (int nb = 0; nb < NT / 2; nb++)
                    ldsm_x4(bf[2 * nb][0], bf[2 * nb][1], bf[2 * nb + 1][0], bf[2 * nb + 1][1],
                            bAddr + nb * (16 * 128));
                #pragma unroll
                for (int mi = 0; mi < MT; mi++)
                    #pragma unroll
                    for (int ni = 0; ni < NT; ni++)
                        mma_f16(acc[t][mi][ni][0], acc[t][mi][ni][1],
                                acc[t][mi][ni][2], acc[t][mi][ni][3],
                                af[mi][0], af[mi][1], af[mi][2], af[mi][3],
                                bf[ni][0], bf[ni][1]);
            }
        }
        __syncthreads();
    }

    float sum0[MT][2], sum1[MT][2];
    #pragma unroll
    for (int mi = 0; mi < MT; mi++)
        sum0[mi][0] = sum0[mi][1] = sum1[mi][0] = sum1[mi][1] = 0.f;

    #pragma unroll
    for (int ni = 0; ni < NT; ni++) {
        const int col = wn * WN + ni * 8 + tig * 2;
        const float pb0r = __ldg(&bias[col]),     pb1r = __ldg(&bias[col + 1]);
        const float pb0i = __ldg(&bias[N + col]), pb1i = __ldg(&bias[N + col + 1]);
        #pragma unroll
        for (int mi = 0; mi < MT; mi++) {
            #pragma unroll
            for (int h = 0; h < 2; h++) {
                float vr0 = acc[0][mi][ni][h * 2 + 0] + pb0r;
                float vr1 = acc[0][mi][ni][h * 2 + 1] + pb1r;
                float vi0 = 1.f / (1.f + expf(-(acc[1][mi][ni][h * 2 + 0] + pb0i)));
                float vi1 = 1.f / (1.f + expf(-(acc[1][mi][ni][h * 2 + 1] + pb1i)));
                acc[0][mi][ni][h * 2 + 0] = vr0;
                acc[0][mi][ni][h * 2 + 1] = vr1;
                acc[1][mi][ni][h * 2 + 0] = vi0;
                acc[1][mi][ni][h * 2 + 1] = vi1;
                sum0[mi][h] += vr0 * vr0 + vi0 * vi0;
                sum1[mi][h] += vr1 * vr1 + vi1 * vi1;
            }
        }
    }
    #pragma unroll
    for (int mi = 0; mi < MT; mi++)
        #pragma unroll
        for (int h = 0; h < 2; h++) {
            #pragma unroll
            for (int off = 1; off <= 2; off <<= 1) {
                sum0[mi][h] += __shfl_xor_sync(0xFFFFFFFFu, sum0[mi][h], off);
                sum1[mi][h] += __shfl_xor_sync(0xFFFFFFFFu, sum1[mi][h], off);
            }
        }
    if (tig == 0) {
        #pragma unroll
        for (int mi = 0; mi < MT; mi++)
            #pragma unroll
            for (int h = 0; h < 2; h++) {
                int rl = wm * 32 + mi * 16 + grp + h * 8;
                ssum[rl * 4 + 0 * 2 + wn] = sum0[mi][h];
                ssum[rl * 4 + 1 * 2 + wn] = sum1[mi][h];
            }
    }
    __syncthreads();

    #pragma unroll
    for (int mi = 0; mi < MT; mi++) {
        #pragma unroll
        for (int h = 0; h < 2; h++) {
            const int rl  = wm * 32 + mi * 16 + grp + h * 8;
            const int row = bm + rl;
            const int b   = row / SUB, s = row % SUB;
            const float inv0 = rsqrtf(ssum[rl * 4 + 0] + ssum[rl * 4 + 1]);
            const float inv1 = rsqrtf(ssum[rl * 4 + 2] + ssum[rl * 4 + 3]);
            #pragma unroll
            for (int ni = 0; ni < NT; ni++) {
                const int col = wn * WN + ni * 8 + tig * 2;
                const int tx  = col >> 1;
                size_t i0 = ((size_t)(b * 64 + 0 * 32 + tx) * SUB + s);
                ((float2*)out)[i0] = make_float2(acc[0][mi][ni][h * 2 + 0] * inv0,
                                                 acc[1][mi][ni][h * 2 + 0] * inv0);
                size_t i1 = ((size_t)(b * 64 + 1 * 32 + tx) * SUB + s);
                ((float2*)out)[i1] = make_float2(acc[0][mi][ni][h * 2 + 1] * inv1,
                                                 acc[1][mi][ni][h * 2 + 1] * inv1);
            }
        }
    }
}

// -------------------- launch --------------------
extern "C" void kernel_launch(void* const* d_in, const int* in_sizes, int n_in,
                              void* d_out, int out_size) {
    const float* V1  = (const float*)d_in[0];
    const float* V2  = (const float*)d_in[1];
    const float* W1  = (const float*)d_in[2];
    const float* b1  = (const float*)d_in[3];
    const float* g1  = (const float*)d_in[4];
    const float* be1 = (const float*)d_in[5];
    const float* m1  = (const float*)d_in[6];
    const float* v1  = (const float*)d_in[7];
    const float* W2  = (const float*)d_in[8];
    const float* b2  = (const float*)d_in[9];
    const float* g2  = (const float*)d_in[10];
    const float* be2 = (const float*)d_in[11];
    const float* m2  = (const float*)d_in[12];
    const float* v2  = (const float*)d_in[13];
    const float* W3  = (const float*)d_in[14];
    const float* b3  = (const float*)d_in[15];
    const float* g3  = (const float*)d_in[16];
    const float* be3 = (const float*)d_in[17];
    const float* m3  = (const float*)d_in[18];
    const float* v3  = (const float*)d_in[19];
    const float* W4  = (const float*)d_in[20];
    const float* b4  = (const float*)d_in[21];

    __half *X, *Abuf, *Bbuf, *W1t, *W2t, *W3t, *W4t;
    cudaGetSymbolAddress((void**)&X,    g_X);
    cudaGetSymbolAddress((void**)&Abuf, g_A);
    cudaGetSymbolAddress((void**)&Bbuf, g_Bf);
    cudaGetSymbolAddress((void**)&W1t,  g_W1t);
    cudaGetSymbolAddress((void**)&W2t,  g_W2t);
    cudaGetSymbolAddress((void**)&W3t,  g_W3t);
    cudaGetSymbolAddress((void**)&W4t,  g_W4t);

    const int SMEM128 = (128 + 128) * 64 * 2 * 3;          // 98304
    const int SMEML1  = 128 * 64 * 2 + 3 * 128 * 64 * 2;   // 65536
    const int SMEM4H  = (64 + 64) * 64 * 2 * 3 + 1024;     // 50176
    cudaFuncSetAttribute(gemm_h<128>, cudaFuncAttributeMaxDynamicSharedMemorySize, SMEM128);
    cudaFuncSetAttribute(gemm_l1,     cudaFuncAttributeMaxDynamicSharedMemorySize, SMEML1);
    cudaFuncSetAttribute(gemm4_head,  cudaFuncAttributeMaxDynamicSharedMemorySize, SMEM4H);

    prologue_kernel<<<R / 4 + 1728, 256>>>(V1, V2, X, W1, W2, W3, W4,
                                           W1t, W2t, W3t, W4t);

    gemm_l1<<<dim3(1, R / 128, 2), 128, SMEML1>>>(
        X, W1t, b1, g1, be1, m1, v1, Abuf);
    gemm_h<128><<<dim3(512 / 128, R / 128, 2), 128, SMEM128>>>(
        Abuf, W2t, b2, g2, be2, m2, v2, Bbuf, 1024, 512);
    gemm_h<128><<<dim3(512 / 128, R / 128, 2), 128, SMEM128>>>(
        Bbuf, W3t, b3, g3, be3, m3, v3, Abuf, 512, 512);

    gemm4_head<<<dim3(1, R / 64, 1), 128, SMEM4H>>>(Abuf, W4t, b4, (float*)d_out);
}

// round 15
// speedup vs baseline: 1.0998x; 1.0998x over previous
#include <cuda_runtime.h>
#include <cuda_fp16.h>
#include <math.h>
#include <cstdint>

#define EPS_BN 1e-3f

static constexpr int B_  = 4096;
static constexpr int TXN = 32;
static constexpr int SUB = 13;
static constexpr int R   = B_ * SUB;   // 53248 rows per tower

// -------------------- scratch (alloc-free: __device__ globals) --------------------
__device__ __half g_X [(size_t)2 * R * 64];
__device__ __half g_A [(size_t)2 * R * 1024];
__device__ __half g_Bf[(size_t)2 * R * 512];
__device__ __half g_W1t[(size_t)2 * 1024 * 64];
__device__ __half g_W2t[(size_t)2 * 512 * 1024];
__device__ __half g_W3t[(size_t)2 * 512 * 512];
__device__ __half g_W4t[(size_t)2 * 64 * 512];

// -------------------- helpers --------------------
__device__ __forceinline__ uint32_t smem_u32(const void* p) {
    uint32_t a;
    asm("{ .reg .u64 t; cvta.to.shared.u64 t, %1; cvt.u32.u64 %0, t; }" : "=r"(a) : "l"(p));
    return a;
}
#define CP16(dst, src) \
    asm volatile("cp.async.cg.shared.global [%0], [%1], 16;" :: "r"(dst), "l"(src))
#define CP_COMMIT() asm volatile("cp.async.commit_group;" ::: "memory")

__device__ __forceinline__ void ldsm_x4(uint32_t& r0, uint32_t& r1, uint32_t& r2,
                                        uint32_t& r3, uint32_t addr) {
    asm volatile("ldmatrix.sync.aligned.m8n8.x4.shared.b16 {%0,%1,%2,%3}, [%4];"
        : "=r"(r0), "=r"(r1), "=r"(r2), "=r"(r3) : "r"(addr));
}
__device__ __forceinline__ void mma_f16(float& c0, float& c1, float& c2, float& c3,
                                        uint32_t a0, uint32_t a1, uint32_t a2, uint32_t a3,
                                        uint32_t b0, uint32_t b1) {
    asm volatile(
        "mma.sync.aligned.m16n8k16.row.col.f32.f16.f16.f32 "
        "{%0,%1,%2,%3}, {%4,%5,%6,%7}, {%8,%9}, {%0,%1,%2,%3};"
        : "+f"(c0), "+f"(c1), "+f"(c2), "+f"(c3)
        : "r"(a0), "r"(a1), "r"(a2), "r"(a3), "r"(b0), "r"(b1));
}

// -------------------- merged prologue: input norm + all weight transposes ---------
__global__ void prologue_kernel(const float* __restrict__ V1, const float* __restrict__ V2,
                                __half* __restrict__ X,
                                const float* __restrict__ W1, const float* __restrict__ W2,
                                const float* __restrict__ W3, const float* __restrict__ W4,
                                __half* __restrict__ W1t, __half* __restrict__ W2t,
                                __half* __restrict__ W3t, __half* __restrict__ W4t) {
    if (blockIdx.x < R / 4) {
        int sub = threadIdx.x >> 6;
        int pair = blockIdx.x * 4 + sub;
        int b = pair / SUB, s = pair % SUB;
        int o = threadIdx.x & 63;
        int warp = o >> 5, lane = o & 31;
        const float* V = (warp == 0) ? V1 : V2;
        int base = ((b * TXN + lane) * SUB + s) * 2;
        float c0 = V[base], c1 = V[base + 1];
        float ss = c0 * c0 + c1 * c1;
        #pragma unroll
        for (int off = 16; off; off >>= 1) ss += __shfl_xor_sync(0xFFFFFFFFu, ss, off);
        float inv = rsqrtf(ss);
        X[((size_t)0 * R + pair) * 64 + o] = __float2half_rn(c0 * inv);
        X[((size_t)1 * R + pair) * 64 + o] = __float2half_rn(c1 * inv);
        return;
    }
    __shared__ float tile[32][33];
    int idx = blockIdx.x - R / 4;
    int t = idx / 864, bid = idx % 864;
    const float* W; __half* Wt; int K, N, rem;
    if (bid < 64)       { W = W1; Wt = W1t; K = 64;   N = 1024; rem = bid; }
    else if (bid < 576) { W = W2; Wt = W2t; K = 1024; N = 512;  rem = bid - 64; }
    else if (bid < 832) { W = W3; Wt = W3t; K = 512;  N = 512;  rem = bid - 576; }
    else                { W = W4; Wt = W4t; K = 512;  N = 64;   rem = bid - 832; }
    int nb = N / 32;
    int k0 = (rem / nb) * 32, n0 = (rem % nb) * 32;
    const float* Wp = W + (size_t)t * K * N;
    __half* Wtp = Wt + (size_t)t * N * K;
    int x = threadIdx.x & 31, y = threadIdx.x >> 5;
    #pragma unroll
    for (int dy = 0; dy < 32; dy += 8)
        tile[y + dy][x] = Wp[(size_t)(k0 + y + dy) * N + n0 + x];
    __syncthreads();
    #pragma unroll
    for (int dy = 0; dy < 32; dy += 8)
        Wtp[(size_t)(n0 + y + dy) * K + k0 + x] = __float2half_rn(tile[x][y + dy]);
}

// -------------------- shared GEMM body (mainloop + bias/ReLU/BN epilogue) ---------
template <int BN>
__device__ __forceinline__ void gemm_body(
        const __half* __restrict__ A, const __half* __restrict__ Wt,
        const float* __restrict__ bias, const float* __restrict__ gg,
        const float* __restrict__ bbe, const float* __restrict__ mm,
        const float* __restrict__ vv, __half* __restrict__ C,
        int K, int N, __half* smem) {
    constexpr int BM = 128, BK = 64, STAGES = 3;
    constexpr int WN = BN / 2;
    constexpr int MT = 4;
    constexpr int NT = WN / 8;
    constexpr int STG_A = BM * BK;
    constexpr int STG   = (BM + BN) * BK;

    const uint32_t sb = smem_u32(smem);

    const int tid  = threadIdx.x;
    const int wid  = tid >> 5, lane = tid & 31;
    const int grp  = lane >> 2, tig = lane & 3;
    const int wm   = wid & 1, wn = wid >> 1;
    const int t    = blockIdx.z;
    const int bm   = blockIdx.y * BM;
    const int bn   = blockIdx.x * BN;

    A  += (size_t)t * R * K;
    Wt += (size_t)t * N * K;
    bias += (size_t)t * N;
    gg += (size_t)t * N; bbe += (size_t)t * N; mm += (size_t)t * N; vv += (size_t)t * N;

    const int iters = K / BK;

    auto load_tiles = [&](int it) {
        const int k0 = it * BK;
        __half* d = smem + (it % STAGES) * STG;
        uint32_t dA = smem_u32(d), dB = dA + STG_A * 2;
        #pragma unroll
        for (int p = 0; p < 8; p++) {
            int idx = p * 128 + tid;
            int r = idx >> 3, c = idx & 7;
            CP16(dA + r * 128 + ((c ^ (r & 7)) << 4),
                 A + (size_t)(bm + r) * K + k0 + c * 8);
        }
        #pragma unroll
        for (int p = 0; p < BN / 16; p++) {
            int idx = p * 128 + tid;
            int r = idx >> 3, c = idx & 7;
            CP16(dB + r * 128 + ((c ^ (r & 7)) << 4),
                 Wt + (size_t)(bn + r) * K + k0 + c * 8);
        }
    };

    float acc[MT][NT][4];
    #pragma unroll
    for (int i = 0; i < MT; i++)
        #pragma unroll
        for (int j = 0; j < NT; j++)
            acc[i][j][0] = acc[i][j][1] = acc[i][j][2] = acc[i][j][3] = 0.f;

    #pragma unroll
    for (int s = 0; s < STAGES - 1; s++) {
        if (s < iters) load_tiles(s);
        CP_COMMIT();
    }

    const int s3     = lane & 7;
    const uint32_t a_rb = (uint32_t)((wm * 64 + (lane & 7) + ((lane >> 3) & 1) * 8) * 128);
    const int a_csel = lane >> 4;
    const uint32_t b_rb = (uint32_t)((wn * WN + (lane & 7) + ((lane >> 4) & 1) * 8) * 128);
    const int b_csel = (lane >> 3) & 1;

    for (int it = 0; it < iters; ++it) {
        asm volatile("cp.async.wait_group 1;" ::: "memory");
        __syncthreads();
        {
            int nxt = it + STAGES - 1;
            if (nxt < iters) load_tiles(nxt);
            CP_COMMIT();
        }

        const uint32_t aB = sb + (it % STAGES) * STG * 2;
        const uint32_t bB = aB + STG_A * 2;

        #pragma unroll
        for (int ks = 0; ks < BK / 16; ks++) {
            const uint32_t aAddr = aB + a_rb + (uint32_t)(((ks * 2 + a_csel) ^ s3) << 4);
            const uint32_t bAddr = bB + b_rb + (uint32_t)(((ks * 2 + b_csel) ^ s3) << 4);
            uint32_t af[MT][4], bf[NT][2];
            #pragma unroll
            for (int mi = 0; mi < MT; mi++)
                ldsm_x4(af[mi][0], af[mi][1], af[mi][2], af[mi][3],
                        aAddr + mi * (16 * 128));
            #pragma unroll
            for (int nb = 0; nb < NT / 2; nb++)
                ldsm_x4(bf[2 * nb][0], bf[2 * nb][1], bf[2 * nb + 1][0], bf[2 * nb + 1][1],
                        bAddr + nb * (16 * 128));
            #pragma unroll
            for (int mi = 0; mi < MT; mi++)
                #pragma unroll
                for (int ni = 0; ni < NT; ni++)
                    mma_f16(acc[mi][ni][0], acc[mi][ni][1], acc[mi][ni][2], acc[mi][ni][3],
                            af[mi][0], af[mi][1], af[mi][2], af[mi][3],
                            bf[ni][0], bf[ni][1]);
        }
    }

    #pragma unroll
    for (int ni = 0; ni < NT; ni++) {
        const int col = bn + wn * WN + ni * 8 + tig * 2;
        float pb0 = __ldg(&bias[col]), pb1 = __ldg(&bias[col + 1]);
        float pm0 = __ldg(&mm[col]),  pm1 = __ldg(&mm[col + 1]);
        float ps0 = __ldg(&gg[col])     * rsqrtf(__ldg(&vv[col])     + EPS_BN);
        float ps1 = __ldg(&gg[col + 1]) * rsqrtf(__ldg(&vv[col + 1]) + EPS_BN);
        float pe0 = __ldg(&bbe[col]), pe1 = __ldg(&bbe[col + 1]);
        #pragma unroll
        for (int mi = 0; mi < MT; mi++) {
            #pragma unroll
            for (int h = 0; h < 2; h++) {
                const int row = bm + wm * 64 + mi * 16 + grp + h * 8;
                float v0 = fmaxf(acc[mi][ni][h * 2 + 0] + pb0, 0.f);
                float v1 = fmaxf(acc[mi][ni][h * 2 + 1] + pb1, 0.f);
                v0 = (v0 - pm0) * ps0 + pe0;
                v1 = (v1 - pm1) * ps1 + pe1;
                *(__half2*)(C + (size_t)t * R * N + (size_t)row * N + col)
                    = __floats2half2_rn(v0, v1);
            }
        }
    }
}

// L2/L3 variant: 2 CTAs/SM (R12-proven mainloop throughput)
__global__ void __launch_bounds__(128, 2)
gemm_h(const __half* __restrict__ A, const __half* __restrict__ Wt,
       const float* __restrict__ bias, const float* __restrict__ gg,
       const float* __restrict__ bbe, const float* __restrict__ mm,
       const float* __restrict__ vv, __half* __restrict__ C, int K, int N) {
    extern __shared__ __half smem[];
    gemm_body<128>(A, Wt, bias, gg, bbe, mm, vv, C, K, N, smem);
}

// L1 variant: 3 CTAs/SM (iters=1 -> only stage 0 used; smem = 1 stage = 32 KB).
// Latency-bound layer: occupancy matters more than per-warp reg budget.
__global__ void __launch_bounds__(128, 3)
gemm_h3(const __half* __restrict__ A, const __half* __restrict__ Wt,
        const float* __restrict__ bias, const float* __restrict__ gg,
        const float* __restrict__ bbe, const float* __restrict__ mm,
        const float* __restrict__ vv, __half* __restrict__ C, int K, int N) {
    extern __shared__ __half smem[];
    gemm_body<128>(A, Wt, bias, gg, bbe, mm, vv, C, K, N, smem);
}

// -------------------- fused layer-4 GEMM (both towers) + sigmoid/L2-norm head -----
// CTA: 64 rows x 64 cols, K=512, towers sequential; 3 CTAs/SM (latency-bound).
__global__ void __launch_bounds__(128, 3)
gemm4_head(const __half* __restrict__ A, const __half* __restrict__ Wt,
           const float* __restrict__ bias, float* __restrict__ out) {
    constexpr int BM = 64, BK = 64, STAGES = 3, K = 512, N = 64;
    constexpr int WN = 32, MT = 2, NT = 4;
    constexpr int STG_A = BM * BK;
    constexpr int STG   = (BM + 64) * BK;
    constexpr int ITERS = K / BK;

    extern __shared__ __half smem[];
    const uint32_t sb = smem_u32(smem);
    float* ssum = (float*)(smem + STAGES * STG);

    const int tid  = threadIdx.x;
    const int wid  = tid >> 5, lane = tid & 31;
    const int grp  = lane >> 2, tig = lane & 3;
    const int wm   = wid & 1, wn = wid >> 1;
    const int bm   = blockIdx.y * BM;

    const int s3     = lane & 7;
    const uint32_t a_rb = (uint32_t)((wm * 32 + (lane & 7) + ((lane >> 3) & 1) * 8) * 128);
    const int a_csel = lane >> 4;
    const uint32_t b_rb = (uint32_t)((wn * WN + (lane & 7) + ((lane >> 4) & 1) * 8) * 128);
    const int b_csel = (lane >> 3) & 1;

    float acc[2][MT][NT][4];
    #pragma unroll
    for (int t = 0; t < 2; t++)
        #pragma unroll
        for (int i = 0; i < MT; i++)
            #pragma unroll
            for (int j = 0; j < NT; j++)
                acc[t][i][j][0] = acc[t][i][j][1] = acc[t][i][j][2] = acc[t][i][j][3] = 0.f;

    auto load_tiles = [&](const __half* Ap, const __half* Wp, int it) {
        const int k0 = it * BK;
        __half* d = smem + (it % STAGES) * STG;
        uint32_t dA = smem_u32(d), dB = dA + STG_A * 2;
        #pragma unroll
        for (int p = 0; p < 4; p++) {
            int idx = p * 128 + tid;
            int r = idx >> 3, c = idx & 7;
            CP16(dA + r * 128 + ((c ^ (r & 7)) << 4),
                 Ap + (size_t)(bm + r) * K + k0 + c * 8);
        }
        #pragma unroll
        for (int p = 0; p < 4; p++) {
            int idx = p * 128 + tid;
            int r = idx >> 3, c = idx & 7;
            CP16(dB + r * 128 + ((c ^ (r & 7)) << 4),
                 Wp + (size_t)r * K + k0 + c * 8);
        }
    };

    #pragma unroll
    for (int t = 0; t < 2; t++) {
        const __half* Ap = A  + (size_t)t * R * K;
        const __half* Wp = Wt + (size_t)t * N * K;

        load_tiles(Ap, Wp, 0); CP_COMMIT();
        load_tiles(Ap, Wp, 1); CP_COMMIT();

        for (int it = 0; it < ITERS; ++it) {
            asm volatile("cp.async.wait_group 1;" ::: "memory");
            __syncthreads();
            {
                int nxt = it + STAGES - 1;
                if (nxt < ITERS) load_tiles(Ap, Wp, nxt);
                CP_COMMIT();
            }
            const uint32_t aB = sb + (it % STAGES) * STG * 2;
            const uint32_t bB = aB + STG_A * 2;
            #pragma unroll
            for (int ks = 0; ks < BK / 16; ks++) {
                const uint32_t aAddr = aB + a_rb + (uint32_t)(((ks * 2 + a_csel) ^ s3) << 4);
                const uint32_t bAddr = bB + b_rb + (uint32_t)(((ks * 2 + b_csel) ^ s3) << 4);
                uint32_t af[MT][4], bf[NT][2];
                #pragma unroll
                for (int mi = 0; mi < MT; mi++)
                    ldsm_x4(af[mi][0], af[mi][1], af[mi][2], af[mi][3],
                            aAddr + mi * (16 * 128));
                #pragma unroll
                for (int nb = 0; nb < NT / 2; nb++)
                    ldsm_x4(bf[2 * nb][0], bf[2 * nb][1], bf[2 * nb + 1][0], bf[2 * nb + 1][1],
                            bAddr + nb * (16 * 128));
                #pragma unroll
                for (int mi = 0; mi < MT; mi++)
                    #pragma unroll
                    for (int ni = 0; ni < NT; ni++)
                        mma_f16(acc[t][mi][ni][0], acc[t][mi][ni][1],
                                acc[t][mi][ni][2], acc[t][mi][ni][3],
                                af[mi][0], af[mi][1], af[mi][2], af[mi][3],
                                bf[ni][0], bf[ni][1]);
            }
        }
        __syncthreads();
    }

    float sum0[MT][2], sum1[MT][2];
    #pragma unroll
    for (int mi = 0; mi < MT; mi++)
        sum0[mi][0] = sum0[mi][1] = sum1[mi][0] = sum1[mi][1] = 0.f;

    #pragma unroll
    for (int ni = 0; ni < NT; ni++) {
        const int col = wn * WN + ni * 8 + tig * 2;
        const float pb0r = __ldg(&bias[col]),     pb1r = __ldg(&bias[col + 1]);
        const float pb0i = __ldg(&bias[N + col]), pb1i = __ldg(&bias[N + col + 1]);
        #pragma unroll
        for (int mi = 0; mi < MT; mi++) {
            #pragma unroll
            for (int h = 0; h < 2; h++) {
                float vr0 = acc[0][mi][ni][h * 2 + 0] + pb0r;
                float vr1 = acc[0][mi][ni][h * 2 + 1] + pb1r;
                float vi0 = 1.f / (1.f + expf(-(acc[1][mi][ni][h * 2 + 0] + pb0i)));
                float vi1 = 1.f / (1.f + expf(-(acc[1][mi][ni][h * 2 + 1] + pb1i)));
                acc[0][mi][ni][h * 2 + 0] = vr0;
                acc[0][mi][ni][h * 2 + 1] = vr1;
                acc[1][mi][ni][h * 2 + 0] = vi0;
                acc[1][mi][ni][h * 2 + 1] = vi1;
                sum0[mi][h] += vr0 * vr0 + vi0 * vi0;
                sum1[mi][h] += vr1 * vr1 + vi1 * vi1;
            }
        }
    }
    #pragma unroll
    for (int mi = 0; mi < MT; mi++)
        #pragma unroll
        for (int h = 0; h < 2; h++) {
            #pragma unroll
            for (int off = 1; off <= 2; off <<= 1) {
                sum0[mi][h] += __shfl_xor_sync(0xFFFFFFFFu, sum0[mi][h], off);
                sum1[mi][h] += __shfl_xor_sync(0xFFFFFFFFu, sum1[mi][h], off);
            }
        }
    if (tig == 0) {
        #pragma unroll
        for (int mi = 0; mi < MT; mi++)
            #pragma unroll
            for (int h = 0; h < 2; h++) {
                int rl = wm * 32 + mi * 16 + grp + h * 8;
                ssum[rl * 4 + 0 * 2 + wn] = sum0[mi][h];
                ssum[rl * 4 + 1 * 2 + wn] = sum1[mi][h];
            }
    }
    __syncthreads();

    #pragma unroll
    for (int mi = 0; mi < MT; mi++) {
        #pragma unroll
        for (int h = 0; h < 2; h++) {
            const int rl  = wm * 32 + mi * 16 + grp + h * 8;
            const int row = bm + rl;
            const int b   = row / SUB, s = row % SUB;
            const float inv0 = rsqrtf(ssum[rl * 4 + 0] + ssum[rl * 4 + 1]);
            const float inv1 = rsqrtf(ssum[rl * 4 + 2] + ssum[rl * 4 + 3]);
            #pragma unroll
            for (int ni = 0; ni < NT; ni++) {
                const int col = wn * WN + ni * 8 + tig * 2;
                const int tx  = col >> 1;
                size_t i0 = ((size_t)(b * 64 + 0 * 32 + tx) * SUB + s);
                ((float2*)out)[i0] = make_float2(acc[0][mi][ni][h * 2 + 0] * inv0,
                                                 acc[1][mi][ni][h * 2 + 0] * inv0);
                size_t i1 = ((size_t)(b * 64 + 1 * 32 + tx) * SUB + s);
                ((float2*)out)[i1] = make_float2(acc[0][mi][ni][h * 2 + 1] * inv1,
                                                 acc[1][mi][ni][h * 2 + 1] * inv1);
            }
        }
    }
}

// -------------------- launch --------------------
extern "C" void kernel_launch(void* const* d_in, const int* in_sizes, int n_in,
                              void* d_out, int out_size) {
    const float* V1  = (const float*)d_in[0];
    const float* V2  = (const float*)d_in[1];
    const float* W1  = (const float*)d_in[2];
    const float* b1  = (const float*)d_in[3];
    const float* g1  = (const float*)d_in[4];
    const float* be1 = (const float*)d_in[5];
    const float* m1  = (const float*)d_in[6];
    const float* v1  = (const float*)d_in[7];
    const float* W2  = (const float*)d_in[8];
    const float* b2  = (const float*)d_in[9];
    const float* g2  = (const float*)d_in[10];
    const float* be2 = (const float*)d_in[11];
    const float* m2  = (const float*)d_in[12];
    const float* v2  = (const float*)d_in[13];
    const float* W3  = (const float*)d_in[14];
    const float* b3  = (const float*)d_in[15];
    const float* g3  = (const float*)d_in[16];
    const float* be3 = (const float*)d_in[17];
    const float* m3  = (const float*)d_in[18];
    const float* v3  = (const float*)d_in[19];
    const float* W4  = (const float*)d_in[20];
    const float* b4  = (const float*)d_in[21];

    __half *X, *Abuf, *Bbuf, *W1t, *W2t, *W3t, *W4t;
    cudaGetSymbolAddress((void**)&X,    g_X);
    cudaGetSymbolAddress((void**)&Abuf, g_A);
    cudaGetSymbolAddress((void**)&Bbuf, g_Bf);
    cudaGetSymbolAddress((void**)&W1t,  g_W1t);
    cudaGetSymbolAddress((void**)&W2t,  g_W2t);
    cudaGetSymbolAddress((void**)&W3t,  g_W3t);
    cudaGetSymbolAddress((void**)&W4t,  g_W4t);

    const int SMEM128 = (128 + 128) * 64 * 2 * 3;          // 98304 (3 stages)
    const int SMEML1  = (128 + 128) * 64 * 2;              // 32768 (1 stage: iters=1)
    const int SMEM4H  = (64 + 64) * 64 * 2 * 3 + 1024;     // 50176
    cudaFuncSetAttribute(gemm_h,     cudaFuncAttributeMaxDynamicSharedMemorySize, SMEM128);
    cudaFuncSetAttribute(gemm_h3,    cudaFuncAttributeMaxDynamicSharedMemorySize, SMEML1);
    cudaFuncSetAttribute(gemm4_head, cudaFuncAttributeMaxDynamicSharedMemorySize, SMEM4H);

    prologue_kernel<<<R / 4 + 1728, 256>>>(V1, V2, X, W1, W2, W3, W4,
                                           W1t, W2t, W3t, W4t);

    // L1: K=64 (iters=1) -> occupancy-3 variant, 1-stage smem
    gemm_h3<<<dim3(1024 / 128, R / 128, 2), 128, SMEML1>>>(
        X, W1t, b1, g1, be1, m1, v1, Abuf, 64, 1024);
    gemm_h<<<dim3(512 / 128, R / 128, 2), 128, SMEM128>>>(
        Abuf, W2t, b2, g2, be2, m2, v2, Bbuf, 1024, 512);
    gemm_h<<<dim3(512 / 128, R / 128, 2), 128, SMEM128>>>(
        Bbuf, W3t, b3, g3, be3, m3, v3, Abuf, 512, 512);

    gemm4_head<<<dim3(1, R / 64, 1), 128, SMEM4H>>>(Abuf, W4t, b4, (float*)d_out);
}